// round 2
// baseline (speedup 1.0000x reference)
#include <cuda_runtime.h>

// Problem constants
#define NPIX 4096      // H*W
#define CC   256       // channels
#define NQ   32        // C/8 (q,k channels)
#define NB   4         // batch
#define ROWS 320       // 32 q + 32 k + 256 v rows of the fused QKV GEMM

// Scratch (static __device__ arrays: allocation-free per harness rules)
__device__ float g_weff[ROWS * CC];                         // folded weights
__device__ float g_beff[ROWS];                              // folded biases
__device__ float g_qkv[(size_t)NB * ROWS * NPIX];           // Q|K|V per batch (~21 MB)

// ---------------------------------------------------------------------------
// Kernel 1: fold depthwise (scale+bias) into the pointwise conv.
//   W_eff[o,c] = pw[o,c] * dw[c];  b_eff[o] = sum_c pw[o,c]*db[c] + pb[o]
// ---------------------------------------------------------------------------
__global__ void fold_kernel(
    const float* __restrict__ dwq, const float* __restrict__ dbq,
    const float* __restrict__ pwq, const float* __restrict__ pbq,
    const float* __restrict__ dwk, const float* __restrict__ dbk,
    const float* __restrict__ pwk, const float* __restrict__ pbk,
    const float* __restrict__ dwv, const float* __restrict__ dbv,
    const float* __restrict__ pwv, const float* __restrict__ pbv)
{
    int o = blockIdx.x;      // 0..319
    int t = threadIdx.x;     // 0..255
    const float *pw, *dw, *db, *pb;
    int oo;
    if (o < 32)      { pw = pwq; dw = dwq; db = dbq; pb = pbq; oo = o; }
    else if (o < 64) { pw = pwk; dw = dwk; db = dbk; pb = pbk; oo = o - 32; }
    else             { pw = pwv; dw = dwv; db = dbv; pb = pbv; oo = o - 64; }

    float w = pw[oo * CC + t];
    g_weff[o * CC + t] = w * dw[t];

    __shared__ float red[256];
    red[t] = w * db[t];
    __syncthreads();
    for (int s = 128; s > 0; s >>= 1) {
        if (t < s) red[t] += red[t + s];
        __syncthreads();
    }
    if (t == 0) g_beff[o] = red[0] + pb[oo];
}

// ---------------------------------------------------------------------------
// Kernel 2: fused QKV GEMM.  qkv[b] = W_eff[320x256] @ X[b][256x4096] + b_eff
// Tiled fp32 GEMM: BM=64, BN=64, BK=16, 256 threads, 4x4 register tile.
// ---------------------------------------------------------------------------
#define QBM 64
#define QBN 64
#define QBK 16

__global__ __launch_bounds__(256) void qkv_kernel(const float* __restrict__ x)
{
    int b  = blockIdx.z;
    int m0 = blockIdx.y * QBM;
    int n0 = blockIdx.x * QBN;
    int t  = threadIdx.x;

    __shared__ float As[QBK][QBM];   // [k][m]
    __shared__ float Bs[QBK][QBN];   // [k][n]

    const float* Xb = x + (size_t)b * CC * NPIX;
    float acc[4][4] = {};
    int tm = t >> 4;          // 0..15 (m groups of 4)
    int tn = t & 15;          // 0..15 (n groups of 4)

    for (int k0 = 0; k0 < CC; k0 += QBK) {
        // load A tile (transposed into [k][m])
        {
            int m  = t >> 2;           // 0..63
            int kq = (t & 3) * 4;      // 0,4,8,12
            float4 v = *(const float4*)&g_weff[(m0 + m) * CC + k0 + kq];
            As[kq + 0][m] = v.x; As[kq + 1][m] = v.y;
            As[kq + 2][m] = v.z; As[kq + 3][m] = v.w;
        }
        // load B tile
        {
            int k  = t >> 4;           // 0..15
            int nq = (t & 15) * 4;     // 0..60
            *(float4*)&Bs[k][nq] = *(const float4*)&Xb[(size_t)(k0 + k) * NPIX + n0 + nq];
        }
        __syncthreads();

        #pragma unroll
        for (int kk = 0; kk < QBK; kk++) {
            float a[4], bb[4];
            *(float4*)a  = *(const float4*)&As[kk][tm * 4];
            *(float4*)bb = *(const float4*)&Bs[kk][tn * 4];
            #pragma unroll
            for (int i = 0; i < 4; i++)
                #pragma unroll
                for (int j = 0; j < 4; j++)
                    acc[i][j] += a[i] * bb[j];
        }
        __syncthreads();
    }

    #pragma unroll
    for (int i = 0; i < 4; i++) {
        int o = m0 + tm * 4 + i;
        float bias = g_beff[o];
        float4 r = make_float4(acc[i][0] + bias, acc[i][1] + bias,
                               acc[i][2] + bias, acc[i][3] + bias);
        *(float4*)&g_qkv[((size_t)b * ROWS + o) * NPIX + n0 + tn * 4] = r;
    }
}

// ---------------------------------------------------------------------------
// Kernel 3: fused flash-style attention + epilogue.
//   energies tiny (|e| ~ 0.1) -> softmax without max subtraction is exact:
//   out[c,i] = (sum_j v[c,j] * exp(e_ij)) / (sum_j exp(e_ij))
//   y = gamma * out + x
// Each CTA: one batch b, 64 query positions i.  256x64 fp32 accumulator in
// registers (8x8 per thread).  K/V streamed through SMEM in j-tiles of 32.
// ---------------------------------------------------------------------------
#define BI  64    // i-tile (queries per CTA)
#define BJ  32    // j-tile
#define VCH 16    // V rows (j) per SMEM chunk

__global__ __launch_bounds__(256, 2) void attn_kernel(
    const float* __restrict__ x, const float* __restrict__ gamma,
    float* __restrict__ out)
{
    int b  = blockIdx.y;
    int i0 = blockIdx.x * BI;
    int t  = threadIdx.x;

    const float* Qb = g_qkv + (size_t)b * ROWS * NPIX;   // rows 0..31
    const float* Kb = Qb + (size_t)32 * NPIX;            // rows 32..63
    const float* Vb = Qb + (size_t)64 * NPIX;            // rows 64..319

    __shared__ float Qs[NQ][BI];      // 8 KB  [c][i]
    __shared__ float Ks[NQ][BJ];      // 4 KB  [c][j]
    __shared__ float Ps[BJ][BI];      // 8 KB  [j][i]
    __shared__ float Vs[VCH][CC];     // 16 KB [j][c]
    __shared__ float Sinv[BI];

    // Load Q tile once: thread -> (c = t/8, 8 consecutive i)
    {
        int c  = t >> 3;
        int io = (t & 7) * 8;
        const float* qr = &Qb[(size_t)c * NPIX + i0 + io];
        *(float4*)&Qs[c][io]     = *(const float4*)&qr[0];
        *(float4*)&Qs[c][io + 4] = *(const float4*)&qr[4];
    }

    float acc[8][8] = {};            // [c][i]
    float s_part[4] = {0.f, 0.f, 0.f, 0.f};

    const int iE = (t & 15) * 4;     // E-phase: 4 i's
    const int jE = (t >> 4) * 2;     //          2 j's
    const int cG = (t >> 3) * 8;     // GEMM: 8 c's
    const int iG = (t & 7) * 8;      //       8 i's

    for (int j0 = 0; j0 < NPIX; j0 += BJ) {
        // load K tile (safe vs. previous GEMM: distinct buffer)
        {
            int c  = t >> 3;
            int jo = (t & 7) * 4;
            *(float4*)&Ks[c][jo] = *(const float4*)&Kb[(size_t)c * NPIX + j0 + jo];
        }
        __syncthreads();   // Ks ready AND previous GEMM done (Ps safe to overwrite)

        // E-phase: P = exp(Q_i . K_j), accumulate row sums
        #pragma unroll
        for (int jj = 0; jj < 2; jj++) {
            int j = jE + jj;
            float e0 = 0.f, e1 = 0.f, e2 = 0.f, e3 = 0.f;
            #pragma unroll
            for (int c = 0; c < NQ; c++) {
                float kv = Ks[c][j];
                float4 q4 = *(const float4*)&Qs[c][iE];
                e0 += q4.x * kv; e1 += q4.y * kv;
                e2 += q4.z * kv; e3 += q4.w * kv;
            }
            float p0 = __expf(e0), p1 = __expf(e1);
            float p2 = __expf(e2), p3 = __expf(e3);
            Ps[j][iE + 0] = p0; Ps[j][iE + 1] = p1;
            Ps[j][iE + 2] = p2; Ps[j][iE + 3] = p3;
            s_part[0] += p0; s_part[1] += p1;
            s_part[2] += p2; s_part[3] += p3;
        }

        // V chunks + accumulate Out[c,i] += V[c,j] * P[j,i]
        #pragma unroll
        for (int vch = 0; vch < BJ; vch += VCH) {
            __syncthreads();   // Ps ready (1st it) / Vs readers done (2nd it)
            {
                // thread t loads 16 consecutive j for channel c=t (64B/thread)
                const float* vg = &Vb[(size_t)t * NPIX + j0 + vch];
                float4 a = *(const float4*)&vg[0];
                float4 bq = *(const float4*)&vg[4];
                float4 cq = *(const float4*)&vg[8];
                float4 dq = *(const float4*)&vg[12];
                Vs[ 0][t] = a.x;  Vs[ 1][t] = a.y;  Vs[ 2][t] = a.z;  Vs[ 3][t] = a.w;
                Vs[ 4][t] = bq.x; Vs[ 5][t] = bq.y; Vs[ 6][t] = bq.z; Vs[ 7][t] = bq.w;
                Vs[ 8][t] = cq.x; Vs[ 9][t] = cq.y; Vs[10][t] = cq.z; Vs[11][t] = cq.w;
                Vs[12][t] = dq.x; Vs[13][t] = dq.y; Vs[14][t] = dq.z; Vs[15][t] = dq.w;
            }
            __syncthreads();   // Vs ready

            #pragma unroll
            for (int jj = 0; jj < VCH; jj++) {
                float p[8], vv[8];
                *(float4*)&p[0]  = *(const float4*)&Ps[vch + jj][iG];
                *(float4*)&p[4]  = *(const float4*)&Ps[vch + jj][iG + 4];
                *(float4*)&vv[0] = *(const float4*)&Vs[jj][cG];
                *(float4*)&vv[4] = *(const float4*)&Vs[jj][cG + 4];
                #pragma unroll
                for (int c = 0; c < 8; c++)
                    #pragma unroll
                    for (int i = 0; i < 8; i++)
                        acc[c][i] += vv[c] * p[i];
            }
        }
        __syncthreads();   // GEMM done before Ks/Ps overwrite next tile
    }

    // Reduce row sums: 16 partials per i (threads sharing iE), via Vs scratch
    {
        float* Sp = &Vs[0][0];      // need 16*64 floats, Vs has 16*256
        int g = t >> 4;             // 0..15
        Sp[g * 64 + iE + 0] = s_part[0];
        Sp[g * 64 + iE + 1] = s_part[1];
        Sp[g * 64 + iE + 2] = s_part[2];
        Sp[g * 64 + iE + 3] = s_part[3];
    }
    __syncthreads();
    if (t < 64) {
        float s = 0.f;
        #pragma unroll
        for (int g = 0; g < 16; g++) s += Vs[0][g * 64 + t];
        Sinv[t] = 1.0f / s;
    }
    __syncthreads();

    // Epilogue: y = gamma * acc / S + x
    float gm = gamma[0];
    float si[8];
    #pragma unroll
    for (int i = 0; i < 8; i++) si[i] = Sinv[iG + i];

    #pragma unroll
    for (int c = 0; c < 8; c++) {
        size_t off = ((size_t)b * CC + (cG + c)) * NPIX + i0 + iG;
        float4 x0 = *(const float4*)&x[off];
        float4 x1 = *(const float4*)&x[off + 4];
        float4 r0, r1;
        r0.x = gm * acc[c][0] * si[0] + x0.x;
        r0.y = gm * acc[c][1] * si[1] + x0.y;
        r0.z = gm * acc[c][2] * si[2] + x0.z;
        r0.w = gm * acc[c][3] * si[3] + x0.w;
        r1.x = gm * acc[c][4] * si[4] + x1.x;
        r1.y = gm * acc[c][5] * si[5] + x1.y;
        r1.z = gm * acc[c][6] * si[6] + x1.z;
        r1.w = gm * acc[c][7] * si[7] + x1.w;
        *(float4*)&out[off]     = r0;
        *(float4*)&out[off + 4] = r1;
    }
}

// ---------------------------------------------------------------------------
extern "C" void kernel_launch(void* const* d_in, const int* in_sizes, int n_in,
                              void* d_out, int out_size)
{
    const float* x     = (const float*)d_in[0];
    const float* dwq   = (const float*)d_in[1];
    const float* dbq   = (const float*)d_in[2];
    const float* pwq   = (const float*)d_in[3];
    const float* pbq   = (const float*)d_in[4];
    const float* dwk   = (const float*)d_in[5];
    const float* dbk   = (const float*)d_in[6];
    const float* pwk   = (const float*)d_in[7];
    const float* pbk   = (const float*)d_in[8];
    const float* dwv   = (const float*)d_in[9];
    const float* dbv   = (const float*)d_in[10];
    const float* pwv   = (const float*)d_in[11];
    const float* pbv   = (const float*)d_in[12];
    const float* gamma = (const float*)d_in[13];
    float* out = (float*)d_out;

    fold_kernel<<<ROWS, 256>>>(dwq, dbq, pwq, pbq,
                               dwk, dbk, pwk, pbk,
                               dwv, dbv, pwv, pbv);
    qkv_kernel<<<dim3(NPIX / QBN, ROWS / QBM, NB), 256>>>(x);
    attn_kernel<<<dim3(NPIX / BI, NB), 256>>>(x, gamma, out);
}

// round 3
// speedup vs baseline: 7.6936x; 7.6936x over previous
#include <cuda_runtime.h>
#include <cuda_bf16.h>
#include <stdint.h>

#define NPIX 4096      // H*W
#define CC   256       // channels
#define NB   4         // batch
#define ROWS 320       // 32 q + 32 k + 256 v

// ---------------- scratch (static __device__: allocation-free) ----------------
__device__ float    g_weff[ROWS * CC];
__device__ float    g_beff[ROWS];
// Q/K packed bf16x2 pairs over channel: [b][c2(32: 0-15=Q,16-31=K)][n]
__device__ uint32_t g_qkp[NB * 32 * NPIX];
// V packed bf16x2 pairs over pixel(j), blocked by j-tile: [b][jt(64)][c(256)][j2(32)]
__device__ uint32_t g_vblk[(size_t)NB * 64 * 256 * 32];

// ---------------------------------------------------------------------------
// helpers
// ---------------------------------------------------------------------------
__device__ __forceinline__ uint32_t smem_addr(const void* p) {
    return (uint32_t)__cvta_generic_to_shared(p);
}
__device__ __forceinline__ void cp_async16(uint32_t dst, const void* src) {
    asm volatile("cp.async.ca.shared.global [%0], [%1], 16;\n" :: "r"(dst), "l"(src));
}
__device__ __forceinline__ void cp_commit() { asm volatile("cp.async.commit_group;\n"); }
template <int N>
__device__ __forceinline__ void cp_wait() { asm volatile("cp.async.wait_group %0;\n" :: "n"(N)); }

__device__ __forceinline__ void mma16816(float* d,
    uint32_t a0, uint32_t a1, uint32_t a2, uint32_t a3, uint32_t b0, uint32_t b1) {
    asm volatile(
        "mma.sync.aligned.m16n8k16.row.col.f32.bf16.bf16.f32 "
        "{%0,%1,%2,%3},{%4,%5,%6,%7},{%8,%9},{%0,%1,%2,%3};\n"
        : "+f"(d[0]), "+f"(d[1]), "+f"(d[2]), "+f"(d[3])
        : "r"(a0), "r"(a1), "r"(a2), "r"(a3), "r"(b0), "r"(b1));
}
__device__ __forceinline__ uint32_t pack_bf2(float lo, float hi) {
    __nv_bfloat162 h = __floats2bfloat162_rn(lo, hi);
    return *reinterpret_cast<uint32_t*>(&h);
}

// ---------------------------------------------------------------------------
// Kernel 1: fold depthwise into pointwise.
// ---------------------------------------------------------------------------
__global__ void fold_kernel(
    const float* __restrict__ dwq, const float* __restrict__ dbq,
    const float* __restrict__ pwq, const float* __restrict__ pbq,
    const float* __restrict__ dwk, const float* __restrict__ dbk,
    const float* __restrict__ pwk, const float* __restrict__ pbk,
    const float* __restrict__ dwv, const float* __restrict__ dbv,
    const float* __restrict__ pwv, const float* __restrict__ pbv)
{
    int o = blockIdx.x, t = threadIdx.x;
    const float *pw, *dw, *db, *pb;
    int oo;
    if (o < 32)      { pw = pwq; dw = dwq; db = dbq; pb = pbq; oo = o; }
    else if (o < 64) { pw = pwk; dw = dwk; db = dbk; pb = pbk; oo = o - 32; }
    else             { pw = pwv; dw = dwv; db = dbv; pb = pbv; oo = o - 64; }

    float w = pw[oo * CC + t];
    g_weff[o * CC + t] = w * dw[t];

    __shared__ float red[256];
    red[t] = w * db[t];
    __syncthreads();
    for (int s = 128; s > 0; s >>= 1) {
        if (t < s) red[t] += red[t + s];
        __syncthreads();
    }
    if (t == 0) g_beff[o] = red[0] + pb[oo];
}

// ---------------------------------------------------------------------------
// Kernel 2: QKV GEMM (SIMT fp32), epilogue writes bf16 in mma-fragment layouts.
// ---------------------------------------------------------------------------
#define QBM 64
#define QBN 64
#define QBK 16

__global__ __launch_bounds__(256) void qkv_kernel(const float* __restrict__ x)
{
    int b  = blockIdx.z;
    int m0 = blockIdx.y * QBM;
    int n0 = blockIdx.x * QBN;
    int t  = threadIdx.x;

    __shared__ float As[QBK][QBM];
    __shared__ float Bs[QBK][QBN];

    const float* Xb = x + (size_t)b * CC * NPIX;
    float acc[4][4] = {};
    int tm = t >> 4;
    int tn = t & 15;

    for (int k0 = 0; k0 < CC; k0 += QBK) {
        {
            int m  = t >> 2;
            int kq = (t & 3) * 4;
            float4 v = *(const float4*)&g_weff[(m0 + m) * CC + k0 + kq];
            As[kq + 0][m] = v.x; As[kq + 1][m] = v.y;
            As[kq + 2][m] = v.z; As[kq + 3][m] = v.w;
        }
        {
            int k  = t >> 4;
            int nq = (t & 15) * 4;
            *(float4*)&Bs[k][nq] = *(const float4*)&Xb[(size_t)(k0 + k) * NPIX + n0 + nq];
        }
        __syncthreads();
        #pragma unroll
        for (int kk = 0; kk < QBK; kk++) {
            float a[4], bb[4];
            *(float4*)a  = *(const float4*)&As[kk][tm * 4];
            *(float4*)bb = *(const float4*)&Bs[kk][tn * 4];
            #pragma unroll
            for (int i = 0; i < 4; i++)
                #pragma unroll
                for (int j = 0; j < 4; j++)
                    acc[i][j] += a[i] * bb[j];
        }
        __syncthreads();
    }

    int n0t = n0 + tn * 4;
    if (m0 == 0) {
        // Q+K rows 0..63 -> pairs over channel: c2 = row/2 (0..31)
        int r0 = tm * 4;
        float b0 = g_beff[r0 + 0], b1 = g_beff[r0 + 1];
        float b2 = g_beff[r0 + 2], b3 = g_beff[r0 + 3];
        uint32_t lo[4], hi[4];
        #pragma unroll
        for (int j = 0; j < 4; j++) {
            lo[j] = pack_bf2(acc[0][j] + b0, acc[1][j] + b1);
            hi[j] = pack_bf2(acc[2][j] + b2, acc[3][j] + b3);
        }
        uint32_t* dst = &g_qkp[((size_t)b * 32 + (r0 >> 1)) * NPIX + n0t];
        *(uint4*)dst          = make_uint4(lo[0], lo[1], lo[2], lo[3]);
        *(uint4*)(dst + NPIX) = make_uint4(hi[0], hi[1], hi[2], hi[3]);
    } else {
        // V rows: pairs over pixel, blocked by j-tile
        int jt = n0 >> 6;
        #pragma unroll
        for (int i = 0; i < 4; i++) {
            int c = m0 - 64 + tm * 4 + i;
            float bias = g_beff[m0 + tm * 4 + i];
            uint2 v;
            v.x = pack_bf2(acc[i][0] + bias, acc[i][1] + bias);
            v.y = pack_bf2(acc[i][2] + bias, acc[i][3] + bias);
            uint32_t* dst = &g_vblk[((((size_t)b * 64 + jt) * 256 + c) * 32) + tn * 2];
            *(uint2*)dst = v;
        }
    }
}

// ---------------------------------------------------------------------------
// Kernel 3: flash-attention with bf16 mma.sync tensor cores.
//   CTA: one batch, 64 queries (i). 8 warps.
//   E-phase: warp w computes E[64i x 8j] (j = w*8..w*8+7), exp -> Ps (bf16x2).
//   PV-phase: warp w computes Out[32c x 64i] (c = 32w..32w+31).
//   Softmax denom in fp32 registers, reduced once at the end.
// SMEM strides padded for conflict-free fragment LDS:
//   Qs/Ks/Ps stride 72 (bank = 8t+g), Vs stride 36 (bank = 4g+t).
// ---------------------------------------------------------------------------
#define SM_QS   0
#define SM_KS   4608
#define SM_PS   13824
#define SM_VS   23040
#define SM_SSUM 96768
#define SM_SINV 97024
#define SM_TOT  97280

__global__ __launch_bounds__(256, 2) void attn_kernel(
    const float* __restrict__ x, const float* __restrict__ gamma,
    float* __restrict__ out)
{
    extern __shared__ char smem[];
    uint32_t* Qs   = (uint32_t*)(smem + SM_QS);    // [16][72]
    uint32_t* Ks   = (uint32_t*)(smem + SM_KS);    // [2][16][72]
    uint32_t* Ps   = (uint32_t*)(smem + SM_PS);    // [32][72]
    uint32_t* Vs   = (uint32_t*)(smem + SM_VS);    // [2][256][36]
    float*    Ssum = (float*)(smem + SM_SSUM);     // [64]
    float*    Sinv = (float*)(smem + SM_SINV);     // [64]

    const int b  = blockIdx.y;
    const int i0 = blockIdx.x * 64;
    const int t  = threadIdx.x;
    const int w  = t >> 5;
    const int lane = t & 31;
    const int g  = lane >> 2;   // groupID
    const int tq = lane & 3;    // threadID in group

    const uint32_t* gq = g_qkp + (size_t)b * 32 * NPIX;       // c2 0..15
    const uint32_t* gk = gq + 16 * NPIX;                       // c2 16..31 (K)
    const uint32_t* gv = g_vblk + (size_t)b * 64 * 256 * 32;

    const uint32_t ks_base = smem_addr(Ks);
    const uint32_t vs_base = smem_addr(Vs);

    if (t < 64) Ssum[t] = 0.f;

    // load Q tile into Qs[c2][i] (pairs over c), stride 72
    {
        int r = t >> 4, c4 = (t & 15) * 4;
        uint4 v = *(const uint4*)&gq[(size_t)r * NPIX + i0 + c4];
        *(uint4*)&Qs[r * 72 + c4] = v;
    }

    // prefetch tile 0
    {
        cp_async16(ks_base + (uint32_t)(((t >> 4) * 72 + (t & 15) * 4) * 4),
                   gk + (t >> 4) * NPIX + (t & 15) * 4);
        const uint32_t* gvt = gv;
        #pragma unroll
        for (int kk = 0; kk < 8; kk++) {
            int idx = t + 256 * kk;
            cp_async16(vs_base + (uint32_t)((((idx >> 3) * 36 + (idx & 7) * 4)) * 4),
                       gvt + idx * 4);
        }
        cp_commit();
    }

    float acc[2][8][4] = {};     // [mt][nt][reg]  (c = 32w+16mt+g(+8), i = 8nt+2tq(+1))
    float ssum[8] = {};          // [mt(4)][row(2)]

    for (int it = 0; it < 64; ++it) {
        int cur = it & 1;
        if (it + 1 < 64) {
            int nxt = cur ^ 1;
            int j0n = (it + 1) * 64;
            cp_async16(ks_base + (uint32_t)((nxt * 16 * 72 + (t >> 4) * 72 + (t & 15) * 4) * 4),
                       gk + (t >> 4) * NPIX + j0n + (t & 15) * 4);
            const uint32_t* gvt = gv + (size_t)(it + 1) * 256 * 32;
            #pragma unroll
            for (int kk = 0; kk < 8; kk++) {
                int idx = t + 256 * kk;
                cp_async16(vs_base + (uint32_t)((nxt * 256 * 36 + (idx >> 3) * 36 + (idx & 7) * 4) * 4),
                           gvt + idx * 4);
            }
            cp_commit();
            cp_wait<1>();
        } else {
            cp_wait<0>();
        }
        __syncthreads();

        // ---------------- E phase: E[64i x 8j], K = 32 channels ----------------
        const uint32_t* Ksb = Ks + cur * 16 * 72;
        float e[4][4] = {};
        #pragma unroll
        for (int ks = 0; ks < 2; ks++) {
            int cb = ks * 8;
            uint32_t kb0 = Ksb[(cb + tq)     * 72 + w * 8 + g];
            uint32_t kb1 = Ksb[(cb + 4 + tq) * 72 + w * 8 + g];
            #pragma unroll
            for (int mt = 0; mt < 4; mt++) {
                uint32_t a0 = Qs[(cb + tq)     * 72 + mt * 16 + g];
                uint32_t a1 = Qs[(cb + tq)     * 72 + mt * 16 + g + 8];
                uint32_t a2 = Qs[(cb + 4 + tq) * 72 + mt * 16 + g];
                uint32_t a3 = Qs[(cb + 4 + tq) * 72 + mt * 16 + g + 8];
                mma16816(e[mt], a0, a1, a2, a3, kb0, kb1);
            }
        }
        // exp (energies tiny -> no max subtraction), write P as bf16x2 pairs over j
        #pragma unroll
        for (int mt = 0; mt < 4; mt++) {
            float p0 = __expf(e[mt][0]), p1 = __expf(e[mt][1]);
            float p2 = __expf(e[mt][2]), p3 = __expf(e[mt][3]);
            ssum[mt * 2 + 0] += p0 + p1;
            ssum[mt * 2 + 1] += p2 + p3;
            Ps[(w * 4 + tq) * 72 + mt * 16 + g]     = pack_bf2(p0, p1);
            Ps[(w * 4 + tq) * 72 + mt * 16 + g + 8] = pack_bf2(p2, p3);
        }
        __syncthreads();

        // ---------------- PV phase: Out[32c x 64i] += V P ----------------
        const uint32_t* Vsb = Vs + cur * 256 * 36;
        int cb0 = w * 32;
        #pragma unroll
        for (int ks = 0; ks < 4; ks++) {
            uint32_t bf0[8], bf1[8];
            #pragma unroll
            for (int nt = 0; nt < 8; nt++) {
                bf0[nt] = Ps[(ks * 8 + tq)     * 72 + nt * 8 + g];
                bf1[nt] = Ps[(ks * 8 + 4 + tq) * 72 + nt * 8 + g];
            }
            #pragma unroll
            for (int mt = 0; mt < 2; mt++) {
                int c = cb0 + mt * 16;
                uint32_t a0 = Vsb[(c + g)     * 36 + ks * 8 + tq];
                uint32_t a1 = Vsb[(c + g + 8) * 36 + ks * 8 + tq];
                uint32_t a2 = Vsb[(c + g)     * 36 + ks * 8 + 4 + tq];
                uint32_t a3 = Vsb[(c + g + 8) * 36 + ks * 8 + 4 + tq];
                #pragma unroll
                for (int nt = 0; nt < 8; nt++)
                    mma16816(acc[mt][nt], a0, a1, a2, a3, bf0[nt], bf1[nt]);
            }
        }
        __syncthreads();
    }

    // softmax denominator reduce
    #pragma unroll
    for (int mt = 0; mt < 4; mt++) {
        atomicAdd(&Ssum[mt * 16 + g],     ssum[mt * 2 + 0]);
        atomicAdd(&Ssum[mt * 16 + g + 8], ssum[mt * 2 + 1]);
    }
    __syncthreads();
    if (t < 64) Sinv[t] = 1.0f / Ssum[t];
    __syncthreads();

    // epilogue: y = gamma * acc / S + x
    float gm = gamma[0];
    #pragma unroll
    for (int mt = 0; mt < 2; mt++) {
        #pragma unroll
        for (int nt = 0; nt < 8; nt++) {
            int irel = nt * 8 + 2 * tq;
            float s0 = Sinv[irel], s1 = Sinv[irel + 1];
            int c0 = w * 32 + mt * 16 + g;
            size_t off = ((size_t)b * CC + c0) * NPIX + i0 + irel;
            float2 xv = *(const float2*)&x[off];
            float2 r;
            r.x = gm * acc[mt][nt][0] * s0 + xv.x;
            r.y = gm * acc[mt][nt][1] * s1 + xv.y;
            *(float2*)&out[off] = r;

            size_t off2 = off + (size_t)8 * NPIX;
            float2 xv2 = *(const float2*)&x[off2];
            float2 r2;
            r2.x = gm * acc[mt][nt][2] * s0 + xv2.x;
            r2.y = gm * acc[mt][nt][3] * s1 + xv2.y;
            *(float2*)&out[off2] = r2;
        }
    }
}

// ---------------------------------------------------------------------------
extern "C" void kernel_launch(void* const* d_in, const int* in_sizes, int n_in,
                              void* d_out, int out_size)
{
    const float* x     = (const float*)d_in[0];
    const float* dwq   = (const float*)d_in[1];
    const float* dbq   = (const float*)d_in[2];
    const float* pwq   = (const float*)d_in[3];
    const float* pbq   = (const float*)d_in[4];
    const float* dwk   = (const float*)d_in[5];
    const float* dbk   = (const float*)d_in[6];
    const float* pwk   = (const float*)d_in[7];
    const float* pbk   = (const float*)d_in[8];
    const float* dwv   = (const float*)d_in[9];
    const float* dbv   = (const float*)d_in[10];
    const float* pwv   = (const float*)d_in[11];
    const float* pbv   = (const float*)d_in[12];
    const float* gamma = (const float*)d_in[13];
    float* out = (float*)d_out;

    cudaFuncSetAttribute(attn_kernel, cudaFuncAttributeMaxDynamicSharedMemorySize, SM_TOT);

    fold_kernel<<<ROWS, 256>>>(dwq, dbq, pwq, pbq,
                               dwk, dbk, pwk, pbk,
                               dwv, dbv, pwv, pbv);
    qkv_kernel<<<dim3(NPIX / QBN, ROWS / QBM, NB), 256>>>(x);
    attn_kernel<<<dim3(NPIX / 64, NB), 256, SM_TOT>>>(x, gamma, out);
}

// round 4
// speedup vs baseline: 9.3359x; 1.2135x over previous
#include <cuda_runtime.h>
#include <cuda_bf16.h>
#include <stdint.h>

#define NPIX 4096      // H*W
#define CC   256       // channels
#define NB   4         // batch
#define ROWS 320       // 32 q + 32 k + 256 v

// ---------------- scratch (static __device__: allocation-free) ----------------
__device__ float g_weff[ROWS * CC];
__device__ float g_beff[ROWS];
// Q,K: [b][n(4096)][c(32)] bf16 (row-per-pixel, 64B rows)
__device__ __nv_bfloat16 g_qb[NB * NPIX * 32];
__device__ __nv_bfloat16 g_kb[NB * NPIX * 32];
// V: [b][jt(64)][c(256)][j(64)] bf16 (per-j-tile, c-major rows of 64 j)
__device__ __nv_bfloat16 g_v[(size_t)NB * 64 * 256 * 64];

// ---------------------------------------------------------------------------
// helpers
// ---------------------------------------------------------------------------
__device__ __forceinline__ uint32_t smem_u32(const void* p) {
    return (uint32_t)__cvta_generic_to_shared(p);
}
__device__ __forceinline__ void cp_async16(uint32_t dst, const void* src) {
    asm volatile("cp.async.ca.shared.global [%0], [%1], 16;\n" :: "r"(dst), "l"(src));
}
__device__ __forceinline__ void cp_commit() { asm volatile("cp.async.commit_group;\n"); }
template <int N>
__device__ __forceinline__ void cp_wait() { asm volatile("cp.async.wait_group %0;\n" :: "n"(N)); }

__device__ __forceinline__ void mma16816(float* d,
    uint32_t a0, uint32_t a1, uint32_t a2, uint32_t a3, uint32_t b0, uint32_t b1) {
    asm volatile(
        "mma.sync.aligned.m16n8k16.row.col.f32.bf16.bf16.f32 "
        "{%0,%1,%2,%3},{%4,%5,%6,%7},{%8,%9},{%0,%1,%2,%3};\n"
        : "+f"(d[0]), "+f"(d[1]), "+f"(d[2]), "+f"(d[3])
        : "r"(a0), "r"(a1), "r"(a2), "r"(a3), "r"(b0), "r"(b1));
}
__device__ __forceinline__ void ldsm4(uint32_t& r0, uint32_t& r1, uint32_t& r2,
                                      uint32_t& r3, uint32_t a) {
    asm volatile("ldmatrix.sync.aligned.m8n8.x4.shared.b16 {%0,%1,%2,%3}, [%4];\n"
        : "=r"(r0), "=r"(r1), "=r"(r2), "=r"(r3) : "r"(a));
}
__device__ __forceinline__ uint32_t pack_bf2(float lo, float hi) {
    __nv_bfloat162 h = __floats2bfloat162_rn(lo, hi);
    return *reinterpret_cast<uint32_t*>(&h);
}

// ---------------------------------------------------------------------------
// Kernel 1: fold depthwise into pointwise.
// ---------------------------------------------------------------------------
__global__ void fold_kernel(
    const float* __restrict__ dwq, const float* __restrict__ dbq,
    const float* __restrict__ pwq, const float* __restrict__ pbq,
    const float* __restrict__ dwk, const float* __restrict__ dbk,
    const float* __restrict__ pwk, const float* __restrict__ pbk,
    const float* __restrict__ dwv, const float* __restrict__ dbv,
    const float* __restrict__ pwv, const float* __restrict__ pbv)
{
    int o = blockIdx.x, t = threadIdx.x;
    const float *pw, *dw, *db, *pb;
    int oo;
    if (o < 32)      { pw = pwq; dw = dwq; db = dbq; pb = pbq; oo = o; }
    else if (o < 64) { pw = pwk; dw = dwk; db = dbk; pb = pbk; oo = o - 32; }
    else             { pw = pwv; dw = dwv; db = dbv; pb = pbv; oo = o - 64; }

    float w = pw[oo * CC + t];
    g_weff[o * CC + t] = w * dw[t];

    __shared__ float red[256];
    red[t] = w * db[t];
    __syncthreads();
    for (int s = 128; s > 0; s >>= 1) {
        if (t < s) red[t] += red[t + s];
        __syncthreads();
    }
    if (t == 0) g_beff[o] = red[0] + pb[oo];
}

// ---------------------------------------------------------------------------
// Kernel 2: QKV GEMM (SIMT fp32). Epilogue emits bf16 in attn-friendly layouts.
// ---------------------------------------------------------------------------
#define QBM 64
#define QBN 64
#define QBK 16

__global__ __launch_bounds__(256) void qkv_kernel(const float* __restrict__ x)
{
    int b  = blockIdx.z;
    int m0 = blockIdx.y * QBM;
    int n0 = blockIdx.x * QBN;
    int t  = threadIdx.x;

    __shared__ float As[QBK][QBM];
    __shared__ float Bs[QBK][QBN];

    const float* Xb = x + (size_t)b * CC * NPIX;
    float acc[4][4] = {};
    int tm = t >> 4;
    int tn = t & 15;

    for (int k0 = 0; k0 < CC; k0 += QBK) {
        {
            int m  = t >> 2;
            int kq = (t & 3) * 4;
            float4 v = *(const float4*)&g_weff[(m0 + m) * CC + k0 + kq];
            As[kq + 0][m] = v.x; As[kq + 1][m] = v.y;
            As[kq + 2][m] = v.z; As[kq + 3][m] = v.w;
        }
        {
            int k  = t >> 4;
            int nq = (t & 15) * 4;
            *(float4*)&Bs[k][nq] = *(const float4*)&Xb[(size_t)(k0 + k) * NPIX + n0 + nq];
        }
        __syncthreads();
        #pragma unroll
        for (int kk = 0; kk < QBK; kk++) {
            float a[4], bb[4];
            *(float4*)a  = *(const float4*)&As[kk][tm * 4];
            *(float4*)bb = *(const float4*)&Bs[kk][tn * 4];
            #pragma unroll
            for (int i = 0; i < 4; i++)
                #pragma unroll
                for (int j = 0; j < 4; j++)
                    acc[i][j] += a[i] * bb[j];
        }
        __syncthreads();
    }

    int n0t = n0 + tn * 4;
    if (m0 == 0) {
        // rows 0..31 = Q, rows 32..63 = K; emit [n][c] bf16 (4 channels/uint2)
        int r0 = tm * 4;
        float b0 = g_beff[r0 + 0], b1 = g_beff[r0 + 1];
        float b2 = g_beff[r0 + 2], b3 = g_beff[r0 + 3];
        __nv_bfloat16* base = (tm < 8) ? g_qb : g_kb;
        int c0 = (tm < 8) ? r0 : (r0 - 32);
        #pragma unroll
        for (int j = 0; j < 4; j++) {
            uint2 v;
            v.x = pack_bf2(acc[0][j] + b0, acc[1][j] + b1);
            v.y = pack_bf2(acc[2][j] + b2, acc[3][j] + b3);
            *(uint2*)&base[((size_t)b * NPIX + n0t + j) * 32 + c0] = v;
        }
    } else {
        // V rows: [b][jt][c][j] bf16, 4 consecutive j per uint2
        int jt = n0 >> 6;
        #pragma unroll
        for (int i = 0; i < 4; i++) {
            int c = m0 - 64 + tm * 4 + i;
            float bias = g_beff[m0 + tm * 4 + i];
            uint2 v;
            v.x = pack_bf2(acc[i][0] + bias, acc[i][1] + bias);
            v.y = pack_bf2(acc[i][2] + bias, acc[i][3] + bias);
            *(uint2*)&g_v[((((size_t)b * 64 + jt) * 256 + c) * 64) + tn * 4] = v;
        }
    }
}

// ---------------------------------------------------------------------------
// Kernel 3: flash attention, FA2-style register-resident P.
//   CTA = 1 batch x 128 queries, 8 warps, each warp owns 16 i.
//   E-phase: E[16i x 64j] (m=i, n=j), Q frags pinned in regs, K via ldmatrix.
//   exp in regs -> P B-frags (k=j, n=i) directly from accumulator layout.
//   PV: Out[256c x 16i] (m=c, n=i), V via ldmatrix from [c][j] SMEM.
// ---------------------------------------------------------------------------
#define SM_Q    0                      // [128][40] bf16 (80B rows)
#define SM_K    10240                  // 3 x [64][40] bf16 (80B rows)
#define SM_V    25600                  // 3 x [256][72] bf16 (144B rows)
#define SM_SINV 136192                 // [8][16] float
#define SM_TOT  136704
#define KBUF    5120
#define VBUF    36864

__global__ __launch_bounds__(256, 1) void attn_kernel(
    const float* __restrict__ x, const float* __restrict__ gamma,
    float* __restrict__ out)
{
    extern __shared__ char smem[];
    const uint32_t sbase = smem_u32(smem);

    const int b    = blockIdx.y;
    const int i0   = blockIdx.x * 128;
    const int t    = threadIdx.x;
    const int w    = t >> 5;
    const int lane = t & 31;
    const int g    = lane >> 2;
    const int tq   = lane & 3;

    const __nv_bfloat16* gq = g_qb + (size_t)b * NPIX * 32;
    const __nv_bfloat16* gk = g_kb + (size_t)b * NPIX * 32;
    const __nv_bfloat16* gv = g_v  + (size_t)b * 64 * 256 * 64;

    // ---- initial async loads: group A = (Q tile + tile0), group B = tile1 ----
    {
        #pragma unroll
        for (int kk = 0; kk < 2; kk++) {
            int idx = t + 256 * kk;                 // 512 chunks
            int row = idx >> 2, c8 = idx & 3;
            cp_async16(sbase + SM_Q + row * 80 + c8 * 16,
                       gq + ((size_t)(i0 + row)) * 32 + c8 * 8);
        }
        { int row = t >> 2, c8 = t & 3;             // K tile 0
          cp_async16(sbase + SM_K + row * 80 + c8 * 16,
                     gk + ((size_t)row) * 32 + c8 * 8); }
        #pragma unroll
        for (int kk = 0; kk < 8; kk++) {            // V tile 0
            int idx = t + 256 * kk;
            int c = idx >> 3, j8 = idx & 7;
            cp_async16(sbase + SM_V + c * 144 + j8 * 16,
                       gv + ((size_t)c) * 64 + j8 * 8);
        }
        cp_commit();
        { int row = t >> 2, c8 = t & 3;             // K tile 1
          cp_async16(sbase + SM_K + KBUF + row * 80 + c8 * 16,
                     gk + ((size_t)(64 + row)) * 32 + c8 * 8); }
        #pragma unroll
        for (int kk = 0; kk < 8; kk++) {            // V tile 1
            int idx = t + 256 * kk;
            int c = idx >> 3, j8 = idx & 7;
            cp_async16(sbase + SM_V + VBUF + c * 144 + j8 * 16,
                       gv + (size_t)1 * 256 * 64 + ((size_t)c) * 64 + j8 * 8);
        }
        cp_commit();
    }

    cp_wait<1>();          // Q + tile0 resident
    __syncthreads();

    // ---- pin Q fragments in registers (m = warp's 16 i, k = 32 c) ----
    uint32_t qa[2][4];
    {
        int row = w * 16 + (lane & 7) + ((lane & 8) ? 8 : 0);
        int cbh = (lane & 16) ? 16 : 0;
        ldsm4(qa[0][0], qa[0][1], qa[0][2], qa[0][3],
              sbase + SM_Q + row * 80 + cbh);
        ldsm4(qa[1][0], qa[1][1], qa[1][2], qa[1][3],
              sbase + SM_Q + row * 80 + 32 + cbh);
    }

    float acc[16][2][4] = {};     // [mt(c16)][nt(i8)][reg]
    float sum_lo = 0.f, sum_hi = 0.f;

    const int l7  = lane & 7;
    const int l8  = (lane & 8) ? 8 : 0;
    const int l16 = (lane & 16) ? 16 : 0;

    for (int it = 0; it < 64; ++it) {
        cp_wait<1>();             // tile it resident
        __syncthreads();          // visibility + all warps done with tile it-1

        // prefetch tile it+2 into buffer (it+2)%3 (freed by the barrier above)
        if (it + 2 < 64) {
            int nb = (it + 2) % 3;
            { int row = t >> 2, c8 = t & 3;
              cp_async16(sbase + SM_K + nb * KBUF + row * 80 + c8 * 16,
                         gk + ((size_t)((it + 2) * 64 + row)) * 32 + c8 * 8); }
            #pragma unroll
            for (int kk = 0; kk < 8; kk++) {
                int idx = t + 256 * kk;
                int c = idx >> 3, j8 = idx & 7;
                cp_async16(sbase + SM_V + nb * VBUF + c * 144 + j8 * 16,
                           gv + (size_t)(it + 2) * 256 * 64 + ((size_t)c) * 64 + j8 * 8);
            }
            cp_commit();
        }

        const uint32_t kb = sbase + SM_K + (it % 3) * KBUF;
        const uint32_t vb = sbase + SM_V + (it % 3) * VBUF;

        // ---------------- E phase: E[16i x 64j], k = 32 c ----------------
        float e[8][4] = {};
        #pragma unroll
        for (int ks = 0; ks < 2; ks++) {
            #pragma unroll
            for (int p = 0; p < 4; p++) {
                uint32_t r0, r1, r2, r3;
                // [j][c] rows: lanes0-7 -> j p*16+0-7 (b0 even jt), 8-15 -> +8 (odd jt)
                ldsm4(r0, r1, r2, r3, kb + (p * 16 + l7 + l8) * 80 + ks * 32 + l16);
                mma16816(e[2 * p],     qa[ks][0], qa[ks][1], qa[ks][2], qa[ks][3], r0, r2);
                mma16816(e[2 * p + 1], qa[ks][0], qa[ks][1], qa[ks][2], qa[ks][3], r1, r3);
            }
        }

        // exp in registers -> P B-fragments (pairs over j, n = i)
        uint32_t pk[8][2];
        #pragma unroll
        for (int jt = 0; jt < 8; jt++) {
            float p0 = __expf(e[jt][0]), p1 = __expf(e[jt][1]);
            float p2 = __expf(e[jt][2]), p3 = __expf(e[jt][3]);
            sum_lo += p0 + p1;
            sum_hi += p2 + p3;
            pk[jt][0] = pack_bf2(p0, p1);
            pk[jt][1] = pack_bf2(p2, p3);
        }

        // ---------------- PV: Out[256c x 16i] += V * P ----------------
        #pragma unroll
        for (int kt = 0; kt < 4; kt++) {
            uint32_t pb0 = pk[2 * kt][0], pb1 = pk[2 * kt + 1][0];   // i 0-7
            uint32_t pc0 = pk[2 * kt][1], pc1 = pk[2 * kt + 1][1];   // i 8-15
            #pragma unroll
            for (int mt = 0; mt < 16; mt++) {
                uint32_t a0, a1, a2, a3;
                ldsm4(a0, a1, a2, a3, vb + (mt * 16 + l7 + l8) * 144 + kt * 32 + l16);
                mma16816(acc[mt][0], a0, a1, a2, a3, pb0, pb1);
                mma16816(acc[mt][1], a0, a1, a2, a3, pc0, pc1);
            }
        }
    }

    // ---- softmax denominators: reduce over the 4 lanes of each row-group ----
    sum_lo += __shfl_xor_sync(0xffffffff, sum_lo, 1);
    sum_lo += __shfl_xor_sync(0xffffffff, sum_lo, 2);
    sum_hi += __shfl_xor_sync(0xffffffff, sum_hi, 1);
    sum_hi += __shfl_xor_sync(0xffffffff, sum_hi, 2);
    float* sv = (float*)(smem + SM_SINV) + w * 16;
    if (tq == 0) {
        sv[g]     = 1.0f / sum_lo;
        sv[g + 8] = 1.0f / sum_hi;
    }
    __syncwarp();
    const float s0 = sv[2 * tq], s1 = sv[2 * tq + 1];
    const float s2 = sv[2 * tq + 8], s3 = sv[2 * tq + 9];

    // ---- epilogue: y = gamma * acc / S + x ----
    const float gm = gamma[0];
    const int iw = i0 + w * 16;
    #pragma unroll
    for (int mt = 0; mt < 16; mt++) {
        int c = mt * 16 + g;
        size_t off = ((size_t)b * CC + c) * NPIX + iw;
        size_t off8 = off + (size_t)8 * NPIX;
        // n-tile 0: i = iw + 2tq(+1)
        {
            float2 xv = *(const float2*)&x[off + 2 * tq];
            float2 r = { gm * acc[mt][0][0] * s0 + xv.x,
                         gm * acc[mt][0][1] * s1 + xv.y };
            *(float2*)&out[off + 2 * tq] = r;
            float2 xv2 = *(const float2*)&x[off8 + 2 * tq];
            float2 r2 = { gm * acc[mt][0][2] * s0 + xv2.x,
                          gm * acc[mt][0][3] * s1 + xv2.y };
            *(float2*)&out[off8 + 2 * tq] = r2;
        }
        // n-tile 1: i = iw + 8 + 2tq(+1)
        {
            float2 xv = *(const float2*)&x[off + 8 + 2 * tq];
            float2 r = { gm * acc[mt][1][0] * s2 + xv.x,
                         gm * acc[mt][1][1] * s3 + xv.y };
            *(float2*)&out[off + 8 + 2 * tq] = r;
            float2 xv2 = *(const float2*)&x[off8 + 8 + 2 * tq];
            float2 r2 = { gm * acc[mt][1][2] * s2 + xv2.x,
                          gm * acc[mt][1][3] * s3 + xv2.y };
            *(float2*)&out[off8 + 8 + 2 * tq] = r2;
        }
    }
}

// ---------------------------------------------------------------------------
extern "C" void kernel_launch(void* const* d_in, const int* in_sizes, int n_in,
                              void* d_out, int out_size)
{
    const float* x     = (const float*)d_in[0];
    const float* dwq   = (const float*)d_in[1];
    const float* dbq   = (const float*)d_in[2];
    const float* pwq   = (const float*)d_in[3];
    const float* pbq   = (const float*)d_in[4];
    const float* dwk   = (const float*)d_in[5];
    const float* dbk   = (const float*)d_in[6];
    const float* pwk   = (const float*)d_in[7];
    const float* pbk   = (const float*)d_in[8];
    const float* dwv   = (const float*)d_in[9];
    const float* dbv   = (const float*)d_in[10];
    const float* pwv   = (const float*)d_in[11];
    const float* pbv   = (const float*)d_in[12];
    const float* gamma = (const float*)d_in[13];
    float* out = (float*)d_out;

    static int init = 0;
    if (!init) {
        cudaFuncSetAttribute(attn_kernel,
            cudaFuncAttributeMaxDynamicSharedMemorySize, SM_TOT);
        init = 1;
    }

    fold_kernel<<<ROWS, 256>>>(dwq, dbq, pwq, pbq,
                               dwk, dbk, pwk, pbk,
                               dwv, dbv, pwv, pbv);
    qkv_kernel<<<dim3(NPIX / QBN, ROWS / QBM, NB), 256>>>(x);
    attn_kernel<<<dim3(NPIX / 128, NB), 256, SM_TOT>>>(x, gamma, out);
}